// round 12
// baseline (speedup 1.0000x reference)
#include <cuda_runtime.h>

// Problem constants
constexpr int C      = 128;            // channels
constexpr int NROW   = 32;             // rows of the similarity matrix
constexpr int P      = 1024;           // pixels per image
constexpr int PPB    = 8;              // pixels per block
constexpr int NBLK   = P / PPB;        // 128 blocks
constexpr int NSTRW  = C * PPB + 8;    // 1032 words per n-row (stride % 32 == 8)
constexpr int NTHR   = 640;            // 20 warps: 10 slots x 2 j-halves
constexpr int NSLOT  = 10;
constexpr int NENT   = NSLOT * 64;     // 640 partial entries = 160 float4

// Scratch (no allocations allowed)
__device__ __align__(16) float g_partial[NBLK * NENT];   // 320 KB
__device__ unsigned int g_counter;                        // zero-init

// Upper-triangle tile pairs (ta<=tb):
// slot: 0:(0,0) 1:(0,1) 2:(0,2) 3:(0,3) 4:(1,1) 5:(1,2) 6:(1,3) 7:(2,2) 8:(2,3) 9:(3,3)
__device__ __constant__ int c_TA[10] = {0,0,0,0,1,1,1,2,2,3};
__device__ __constant__ int c_TB[10] = {0,1,2,3,1,2,3,2,3,3};
__device__ __constant__ int c_SLOT[16] = {0,1,2,3, 1,4,5,6, 2,5,7,8, 3,6,8,9};

#define FFMA2(acc, a, b) \
    asm("fma.rn.f32x2 %0, %1, %2, %0;" : "+l"(acc) : "l"(a), "l"(b))
#define ADDX2(d, a, b) \
    asm("add.rn.f32x2 %0, %1, %2;" : "=l"(d) : "l"(a), "l"(b))
#define LDS64(d, addr) \
    asm volatile("ld.shared.b64 %0, [%1];" : "=l"(d) : "r"(addr))

// ---------------------------------------------------------------------------
// Single fused kernel (1 block/SM, 8 pixels/block), last-block-finish tail:
//   Phase 1: 640 threads load 13 float4 each, exp in regs, STS.128 into
//            zs[n][c][pix8] (conflict-free).
//   Phase 2 (warps 0-7): per-(n,pix) softmax sums -> rs=1/s, ai=q/s^2,
//            overlapped with warps 8-19 starting the Gram.
//   Phase 3: packed f32x2 Gram. Warp = (slot, j-half); lane = (cq, pp).
//   Phase 4: 3-step reduce-scatter over cq -> lane owns (i=ti+cq, 4 j's).
//   Phase 5: d2 = ai+aj-2*rs_i*rs_j*dot; sqrt; pixel sums; write partials.
//   Phase 6: atomicInc ticket (HW-wrapping, self-resetting); LAST block
//            reduces all 128 partial sets in fixed order (deterministic) in
//            reused smem, then warp 0 computes the loss.
// ---------------------------------------------------------------------------
__global__ void __launch_bounds__(NTHR, 1) fused_kernel(
    const float* __restrict__ zi1, const float* __restrict__ zi2,
    const float* __restrict__ zj1, const float* __restrict__ zj2,
    float* __restrict__ out)
{
    extern __shared__ float zs[];            // [32 n][1032 w]; reused by tail
    __shared__ float sA[NROW * PPB];         // [n*8+pix] q/s^2
    __shared__ float sR[NROW * PPB];         // [n*8+pix] 1/s
    __shared__ unsigned int sticket;
    const int t  = threadIdx.x;
    const int p0 = blockIdx.x * PPB;

    // ---- Phase 1: load (16 lines/instr) + exp + STS.128 ---------------------
    {
        float4 v[13];
        #pragma unroll
        for (int q = 0; q < 13; q++) {
            const int g = t + q * NTHR;      // float4 index, 0..8191 valid
            if (g < 8192) {
                const int n = g >> 8;
                const int rem = g & 255;
                const int c = rem >> 1;
                const int h = rem & 1;
                const float* s = (n < 16) ? (n < 8 ? zi1 : zi2)
                                          : (n < 24 ? zj1 : zj2);
                v[q] = *(const float4*)(s + (((n & 7) * C + c) << 10) + p0 + h * 4);
            }
        }
        #pragma unroll
        for (int q = 0; q < 13; q++) {
            const int g = t + q * NTHR;
            if (g < 8192) {
                const int n = g >> 8;
                const int rem = g & 255;
                const int c = rem >> 1;
                const int h = rem & 1;
                float4 e;
                e.x = __expf(v[q].x); e.y = __expf(v[q].y);
                e.z = __expf(v[q].z); e.w = __expf(v[q].w);
                *(float4*)(zs + n * NSTRW + c * 8 + h * 4) = e;
            }
        }
    }
    __syncthreads();

    // ---- Phase 2 (threads 0-255): softmax sums per (n,pix) ------------------
    if (t < NROW * PPB) {
        const int n   = t >> 3;
        const int pix = t & 7;
        const float* col = zs + n * NSTRW + pix;
        float s0 = 0.f, s1 = 0.f, q0 = 0.f, q1 = 0.f;
        #pragma unroll 8
        for (int c = 0; c < C; c += 2) {
            const float va = col[c * 8];
            const float vb = col[(c + 1) * 8];
            s0 += va; q0 = fmaf(va, va, q0);
            s1 += vb; q1 = fmaf(vb, vb, q1);
        }
        const float rs = __fdividef(1.f, s0 + s1);
        sR[t] = rs;                          // t == n*8 + pix
        sA[t] = (q0 + q1) * rs * rs;
    }

    // ---- Phase 3: packed per-pixel-pair Gram --------------------------------
    const int w    = t >> 5;
    const int lane = t & 31;
    const int cq   = lane >> 2;
    const int pp   = lane & 3;               // pixel pair: pixels 2pp, 2pp+1
    const int slot = w >> 1;
    const int jh   = w & 1;
    const int ti   = c_TA[slot] * 8;
    const int tj   = c_TB[slot] * 8 + jh * 4;

    unsigned int zb;
    asm("{ .reg .u64 tt; cvta.to.shared.u64 tt, %1; cvt.u32.u64 %0, tt; }"
        : "=r"(zb) : "l"(zs));
    const unsigned int abase = zb + (unsigned)(ti * NSTRW + cq * 8 + pp * 2) * 4u;
    const unsigned int bbase = zb + (unsigned)(tj * NSTRW + cq * 8 + pp * 2) * 4u;

    unsigned long long acc2[32];
    #pragma unroll
    for (int e = 0; e < 32; e++) acc2[e] = 0ull;

    #pragma unroll 1
    for (int cc = 0; cc < 16; cc++) {
        unsigned long long a2[8], b2[4];
        const unsigned int ao = abase + cc * 256u;
        const unsigned int bo = bbase + cc * 256u;
        #pragma unroll
        for (int k = 0; k < 8; k++) LDS64(a2[k], ao + k * (NSTRW * 4));
        #pragma unroll
        for (int l = 0; l < 4; l++) LDS64(b2[l], bo + l * (NSTRW * 4));
        #pragma unroll
        for (int k = 0; k < 8; k++)
            #pragma unroll
            for (int l = 0; l < 4; l++)
                FFMA2(acc2[k * 4 + l], a2[k], b2[l]);
    }
    __syncthreads();                         // publishes sA/sR (phase 2)

    // ---- Phase 4: reduce-scatter over cq (lane bits 4,3,2) ------------------
    {
        const bool h2 = (lane & 16) != 0;
        #pragma unroll
        for (int i = 0; i < 16; i++) {
            const unsigned long long keep = h2 ? acc2[i + 16] : acc2[i];
            const unsigned long long send = h2 ? acc2[i]      : acc2[i + 16];
            const unsigned long long r = __shfl_xor_sync(0xFFFFFFFFu, send, 16);
            ADDX2(acc2[i], keep, r);
        }
        const bool h1 = (lane & 8) != 0;
        #pragma unroll
        for (int i = 0; i < 8; i++) {
            const unsigned long long keep = h1 ? acc2[i + 8] : acc2[i];
            const unsigned long long send = h1 ? acc2[i]     : acc2[i + 8];
            const unsigned long long r = __shfl_xor_sync(0xFFFFFFFFu, send, 8);
            ADDX2(acc2[i], keep, r);
        }
        const bool h0 = (lane & 4) != 0;
        #pragma unroll
        for (int i = 0; i < 4; i++) {
            const unsigned long long keep = h0 ? acc2[i + 4] : acc2[i];
            const unsigned long long send = h0 ? acc2[i]     : acc2[i + 4];
            const unsigned long long r = __shfl_xor_sync(0xFFFFFFFFu, send, 4);
            ADDX2(acc2[i], keep, r);
        }
    }

    // ---- Phase 5: normalize, d2 -> sqrt, pixel sums, write partials ---------
    {
        const float2 rsi = *(const float2*)(sR + (ti + cq) * PPB + pp * 2);
        const float2 ai  = *(const float2*)(sA + (ti + cq) * PPB + pp * 2);
        float vsum[4];
        #pragma unroll
        for (int l = 0; l < 4; l++) {
            const float2 rsj = *(const float2*)(sR + (tj + l) * PPB + pp * 2);
            const float2 aj  = *(const float2*)(sA + (tj + l) * PPB + pp * 2);
            float dx, dy;
            asm("mov.b64 {%0, %1}, %2;" : "=f"(dx), "=f"(dy) : "l"(acc2[l]));
            float d2x = fmaf(-2.f * (rsi.x * rsj.x), dx, ai.x + aj.x);
            float d2y = fmaf(-2.f * (rsi.y * rsj.y), dy, ai.y + aj.y);
            d2x = fmaxf(d2x, 0.f);
            d2y = fmaxf(d2y, 0.f);
            float sx, sy;
            asm("sqrt.approx.f32 %0, %1;" : "=f"(sx) : "f"(d2x));
            asm("sqrt.approx.f32 %0, %1;" : "=f"(sy) : "f"(d2y));
            vsum[l] = sx + sy;
        }
        #pragma unroll
        for (int l = 0; l < 4; l++) {
            float v = vsum[l];
            v += __shfl_xor_sync(0xFFFFFFFFu, v, 1);
            v += __shfl_xor_sync(0xFFFFFFFFu, v, 2);
            vsum[l] = v;                     // sum over all 8 pixels
        }
        if (pp == 0) {
            float* gp = g_partial + blockIdx.x * NENT
                      + slot * 64 + cq * 8 + jh * 4;
            *(float4*)gp = make_float4(vsum[0], vsum[1], vsum[2], vsum[3]);
        }
    }

    // ---- Phase 6: HW-wrapping ticket; last block reduces + loss -------------
    __threadfence();                         // publish this block's partials
    __syncthreads();                         // all warps' writes issued+fenced
    if (t == 0)
        sticket = atomicInc(&g_counter, NBLK - 1);  // wraps to 0 on last
    __syncthreads();
    if (sticket != NBLK - 1) return;

    __threadfence();                         // acquire all blocks' partials

    // 640 threads: f4-entry = t % 160, block-quarter bg = t / 160.
    // Fixed summation order regardless of which block runs this -> determinism.
    float4* zp = (float4*)zs;                // reuse dynamic smem
    {
        const int f4 = t % 160;
        const int bg = t / 160;
        const float4* src = (const float4*)g_partial + bg * 32 * 160 + f4;
        float4 a0 = make_float4(0.f,0.f,0.f,0.f), a1 = a0, a2 = a0, a3 = a0;
        #pragma unroll
        for (int b = 0; b < 32; b += 4) {
            const float4 v0 = src[(b + 0) * 160];
            const float4 v1 = src[(b + 1) * 160];
            const float4 v2 = src[(b + 2) * 160];
            const float4 v3 = src[(b + 3) * 160];
            a0.x += v0.x; a0.y += v0.y; a0.z += v0.z; a0.w += v0.w;
            a1.x += v1.x; a1.y += v1.y; a1.z += v1.z; a1.w += v1.w;
            a2.x += v2.x; a2.y += v2.y; a2.z += v2.z; a2.w += v2.w;
            a3.x += v3.x; a3.y += v3.y; a3.z += v3.z; a3.w += v3.w;
        }
        float4 r;
        r.x = (a0.x + a1.x) + (a2.x + a3.x);
        r.y = (a0.y + a1.y) + (a2.y + a3.y);
        r.z = (a0.z + a1.z) + (a2.z + a3.z);
        r.w = (a0.w + a1.w) + (a2.w + a3.w);
        zp[bg * 160 + f4] = r;
    }
    __syncthreads();

    float* dist = zs + 4 * 160 * 4;          // 640 floats after the 4x160 f4
    if (t < 160) {
        float4 s = make_float4(0.f, 0.f, 0.f, 0.f);
        #pragma unroll
        for (int bg = 0; bg < 4; bg++) {
            const float4 v = zp[bg * 160 + t];
            s.x += v.x; s.y += v.y; s.z += v.z; s.w += v.w;
        }
        const float sc = 1.f / 1024.f;
        s.x *= sc; s.y *= sc; s.z *= sc; s.w *= sc;
        *(float4*)(dist + t * 4) = s;
    }
    __syncthreads();

    if (t < 32) {
        const int r2 = t;
        const int ra = r2 >> 3;
        float row[32];
        #pragma unroll
        for (int j = 0; j < 32; j++) {
            const int b = j >> 3;
            const int s = c_SLOT[ra * 4 + b];
            const int e = (ra <= b) ? ((r2 & 7) * 8 + (j & 7))
                                    : ((j & 7) * 8 + (r2 & 7));
            row[j] = __expf(-dist[s * 64 + e]);
        }
        const int pr = r2 ^ 16;              // positive partner (K=16)
        const float pos = row[pr];
        float m = pos;
        #pragma unroll
        for (int j = 0; j < 32; j++)
            if (j != r2 && j != pr) m = fmaxf(m, row[j]);
        float s = __expf(pos - m);
        #pragma unroll
        for (int j = 0; j < 32; j++)
            if (j != r2 && j != pr) s += __expf(row[j] - m);
        float rl = __logf(s) + m - pos;      // logsumexp - logits[:,0]

        #pragma unroll
        for (int off = 16; off > 0; off >>= 1)
            rl += __shfl_down_sync(0xFFFFFFFFu, rl, off);

        if (r2 == 0) out[0] = rl * (1.f / 32.f);
    }
}

// ---------------------------------------------------------------------------
extern "C" void kernel_launch(void* const* d_in, const int* in_sizes, int n_in,
                              void* d_out, int out_size)
{
    (void)in_sizes; (void)n_in; (void)out_size;
    const float* zi1 = (const float*)d_in[0];
    const float* zi2 = (const float*)d_in[1];
    const float* zj1 = (const float*)d_in[2];
    const float* zj2 = (const float*)d_in[3];
    float* out = (float*)d_out;

    const int smem = NROW * NSTRW * (int)sizeof(float);  // 132096 B dynamic
    cudaFuncSetAttribute(fused_kernel,
                         cudaFuncAttributeMaxDynamicSharedMemorySize, smem);

    fused_kernel<<<NBLK, NTHR, smem>>>(zi1, zi2, zj1, zj2, out);
}

// round 13
// speedup vs baseline: 1.0389x; 1.0389x over previous
#include <cuda_runtime.h>

// Problem constants
constexpr int C      = 128;            // channels
constexpr int NROW   = 32;             // rows of the similarity matrix
constexpr int P      = 1024;           // pixels per image
constexpr int PPB    = 8;              // pixels per block
constexpr int NBLK   = P / PPB;        // 128 blocks
constexpr int NSTRW  = C * PPB + 8;    // 1032 words per n-row (stride % 32 == 8)
constexpr int NTHR   = 640;            // 20 warps: 10 slots x 2 j-halves
constexpr int NSLOT  = 10;
constexpr int NENT   = NSLOT * 64;     // 640 partial entries = 160 float4

// Scratch (no allocations allowed)
__device__ __align__(16) float g_partial[NBLK * NENT];   // 320 KB

// Upper-triangle tile pairs (ta<=tb):
// slot: 0:(0,0) 1:(0,1) 2:(0,2) 3:(0,3) 4:(1,1) 5:(1,2) 6:(1,3) 7:(2,2) 8:(2,3) 9:(3,3)
__device__ __constant__ int c_TA[10] = {0,0,0,0,1,1,1,2,2,3};
__device__ __constant__ int c_TB[10] = {0,1,2,3,1,2,3,2,3,3};
__device__ __constant__ int c_SLOT[16] = {0,1,2,3, 1,4,5,6, 2,5,7,8, 3,6,8,9};

#define FFMA2(acc, a, b) \
    asm("fma.rn.f32x2 %0, %1, %2, %0;" : "+l"(acc) : "l"(a), "l"(b))
#define ADDX2(d, a, b) \
    asm("add.rn.f32x2 %0, %1, %2;" : "=l"(d) : "l"(a), "l"(b))
#define LDS64(d, addr) \
    asm volatile("ld.shared.b64 %0, [%1];" : "=l"(d) : "r"(addr))

// ---------------------------------------------------------------------------
// Fused kernel (1 block/SM, 8 pixels/block) — proven round-10 body:
//   Phase 1: 640 threads load 13 float4 each, exp in regs, STS.128 into
//            zs[n][c][pix8] (conflict-free).
//   Phase 2 (warps 0-7): per-(n,pix) softmax sums -> rs=1/s, ai=q/s^2,
//            overlapped with warps 8-19 starting the Gram.
//   Phase 3: packed f32x2 Gram. Warp = (slot, j-half); lane = (cq, pp).
//   Phase 4: 3-step reduce-scatter over cq -> lane owns (i=ti+cq, 4 j's).
//   Phase 5: d2 = ai+aj-2*rs_i*rs_j*dot; sqrt; pixel sums; write partials.
// ---------------------------------------------------------------------------
__global__ void __launch_bounds__(NTHR, 1) fused_kernel(
    const float* __restrict__ zi1, const float* __restrict__ zi2,
    const float* __restrict__ zj1, const float* __restrict__ zj2)
{
    extern __shared__ float zs[];            // [32 n][1032 w]
    __shared__ float sA[NROW * PPB];         // [n*8+pix] q/s^2
    __shared__ float sR[NROW * PPB];         // [n*8+pix] 1/s
    const int t  = threadIdx.x;
    const int p0 = blockIdx.x * PPB;

    // ---- Phase 1: load (16 lines/instr) + exp + STS.128 ---------------------
    {
        float4 v[13];
        #pragma unroll
        for (int q = 0; q < 13; q++) {
            const int g = t + q * NTHR;      // float4 index, 0..8191 valid
            if (g < 8192) {
                const int n = g >> 8;
                const int rem = g & 255;
                const int c = rem >> 1;
                const int h = rem & 1;
                const float* s = (n < 16) ? (n < 8 ? zi1 : zi2)
                                          : (n < 24 ? zj1 : zj2);
                v[q] = *(const float4*)(s + (((n & 7) * C + c) << 10) + p0 + h * 4);
            }
        }
        #pragma unroll
        for (int q = 0; q < 13; q++) {
            const int g = t + q * NTHR;
            if (g < 8192) {
                const int n = g >> 8;
                const int rem = g & 255;
                const int c = rem >> 1;
                const int h = rem & 1;
                float4 e;
                e.x = __expf(v[q].x); e.y = __expf(v[q].y);
                e.z = __expf(v[q].z); e.w = __expf(v[q].w);
                *(float4*)(zs + n * NSTRW + c * 8 + h * 4) = e;
            }
        }
    }
    __syncthreads();

    // ---- Phase 2 (threads 0-255): softmax sums per (n,pix) ------------------
    if (t < NROW * PPB) {
        const int n   = t >> 3;
        const int pix = t & 7;
        const float* col = zs + n * NSTRW + pix;
        float s0 = 0.f, s1 = 0.f, q0 = 0.f, q1 = 0.f;
        #pragma unroll 8
        for (int c = 0; c < C; c += 2) {
            const float va = col[c * 8];
            const float vb = col[(c + 1) * 8];
            s0 += va; q0 = fmaf(va, va, q0);
            s1 += vb; q1 = fmaf(vb, vb, q1);
        }
        const float rs = __fdividef(1.f, s0 + s1);
        sR[t] = rs;                          // t == n*8 + pix
        sA[t] = (q0 + q1) * rs * rs;
    }

    // ---- Phase 3: packed per-pixel-pair Gram --------------------------------
    const int w    = t >> 5;
    const int lane = t & 31;
    const int cq   = lane >> 2;
    const int pp   = lane & 3;               // pixel pair: pixels 2pp, 2pp+1
    const int slot = w >> 1;
    const int jh   = w & 1;
    const int ti   = c_TA[slot] * 8;
    const int tj   = c_TB[slot] * 8 + jh * 4;

    unsigned int zb;
    asm("{ .reg .u64 tt; cvta.to.shared.u64 tt, %1; cvt.u32.u64 %0, tt; }"
        : "=r"(zb) : "l"(zs));
    const unsigned int abase = zb + (unsigned)(ti * NSTRW + cq * 8 + pp * 2) * 4u;
    const unsigned int bbase = zb + (unsigned)(tj * NSTRW + cq * 8 + pp * 2) * 4u;

    unsigned long long acc2[32];
    #pragma unroll
    for (int e = 0; e < 32; e++) acc2[e] = 0ull;

    #pragma unroll 1
    for (int cc = 0; cc < 16; cc++) {
        unsigned long long a2[8], b2[4];
        const unsigned int ao = abase + cc * 256u;
        const unsigned int bo = bbase + cc * 256u;
        #pragma unroll
        for (int k = 0; k < 8; k++) LDS64(a2[k], ao + k * (NSTRW * 4));
        #pragma unroll
        for (int l = 0; l < 4; l++) LDS64(b2[l], bo + l * (NSTRW * 4));
        #pragma unroll
        for (int k = 0; k < 8; k++)
            #pragma unroll
            for (int l = 0; l < 4; l++)
                FFMA2(acc2[k * 4 + l], a2[k], b2[l]);
    }
    __syncthreads();                         // publishes sA/sR (phase 2)

    // ---- Phase 4: reduce-scatter over cq (lane bits 4,3,2) ------------------
    {
        const bool h2 = (lane & 16) != 0;
        #pragma unroll
        for (int i = 0; i < 16; i++) {
            const unsigned long long keep = h2 ? acc2[i + 16] : acc2[i];
            const unsigned long long send = h2 ? acc2[i]      : acc2[i + 16];
            const unsigned long long r = __shfl_xor_sync(0xFFFFFFFFu, send, 16);
            ADDX2(acc2[i], keep, r);
        }
        const bool h1 = (lane & 8) != 0;
        #pragma unroll
        for (int i = 0; i < 8; i++) {
            const unsigned long long keep = h1 ? acc2[i + 8] : acc2[i];
            const unsigned long long send = h1 ? acc2[i]     : acc2[i + 8];
            const unsigned long long r = __shfl_xor_sync(0xFFFFFFFFu, send, 8);
            ADDX2(acc2[i], keep, r);
        }
        const bool h0 = (lane & 4) != 0;
        #pragma unroll
        for (int i = 0; i < 4; i++) {
            const unsigned long long keep = h0 ? acc2[i + 4] : acc2[i];
            const unsigned long long send = h0 ? acc2[i]     : acc2[i + 4];
            const unsigned long long r = __shfl_xor_sync(0xFFFFFFFFu, send, 4);
            ADDX2(acc2[i], keep, r);
        }
    }

    // ---- Phase 5: normalize, d2 -> sqrt, pixel sums, write partials ---------
    {
        const float2 rsi = *(const float2*)(sR + (ti + cq) * PPB + pp * 2);
        const float2 ai  = *(const float2*)(sA + (ti + cq) * PPB + pp * 2);
        float vsum[4];
        #pragma unroll
        for (int l = 0; l < 4; l++) {
            const float2 rsj = *(const float2*)(sR + (tj + l) * PPB + pp * 2);
            const float2 aj  = *(const float2*)(sA + (tj + l) * PPB + pp * 2);
            float dx, dy;
            asm("mov.b64 {%0, %1}, %2;" : "=f"(dx), "=f"(dy) : "l"(acc2[l]));
            float d2x = fmaf(-2.f * (rsi.x * rsj.x), dx, ai.x + aj.x);
            float d2y = fmaf(-2.f * (rsi.y * rsj.y), dy, ai.y + aj.y);
            d2x = fmaxf(d2x, 0.f);
            d2y = fmaxf(d2y, 0.f);
            float sx, sy;
            asm("sqrt.approx.f32 %0, %1;" : "=f"(sx) : "f"(d2x));
            asm("sqrt.approx.f32 %0, %1;" : "=f"(sy) : "f"(d2y));
            vsum[l] = sx + sy;
        }
        #pragma unroll
        for (int l = 0; l < 4; l++) {
            float v = vsum[l];
            v += __shfl_xor_sync(0xFFFFFFFFu, v, 1);
            v += __shfl_xor_sync(0xFFFFFFFFu, v, 2);
            vsum[l] = v;                     // sum over all 8 pixels
        }
        if (pp == 0) {
            float* gp = g_partial + blockIdx.x * NENT
                      + slot * 64 + cq * 8 + jh * 4;
            *(float4*)gp = make_float4(vsum[0], vsum[1], vsum[2], vsum[3]);
        }
    }
}

// ---------------------------------------------------------------------------
// Tail kernel: ONE block, 640 threads. Thread = (f4-entry, block-quarter):
// 32 coalesced LDG.128 in 4 chains -> smem; combine quarters; one-warp loss.
// Fixed summation order -> deterministic. No atomics, no fences.
// ---------------------------------------------------------------------------
__global__ __launch_bounds__(640) void tail_kernel(float* __restrict__ out)
{
    __shared__ __align__(16) float4 zp[4 * 160];
    __shared__ float dist[NENT];
    const int t = threadIdx.x;

    {
        const int f4 = t % 160;
        const int bg = t / 160;
        const float4* src = (const float4*)g_partial + bg * 32 * 160 + f4;
        float4 a0 = make_float4(0.f,0.f,0.f,0.f), a1 = a0, a2 = a0, a3 = a0;
        #pragma unroll
        for (int b = 0; b < 32; b += 4) {
            const float4 v0 = src[(b + 0) * 160];
            const float4 v1 = src[(b + 1) * 160];
            const float4 v2 = src[(b + 2) * 160];
            const float4 v3 = src[(b + 3) * 160];
            a0.x += v0.x; a0.y += v0.y; a0.z += v0.z; a0.w += v0.w;
            a1.x += v1.x; a1.y += v1.y; a1.z += v1.z; a1.w += v1.w;
            a2.x += v2.x; a2.y += v2.y; a2.z += v2.z; a2.w += v2.w;
            a3.x += v3.x; a3.y += v3.y; a3.z += v3.z; a3.w += v3.w;
        }
        float4 r;
        r.x = (a0.x + a1.x) + (a2.x + a3.x);
        r.y = (a0.y + a1.y) + (a2.y + a3.y);
        r.z = (a0.z + a1.z) + (a2.z + a3.z);
        r.w = (a0.w + a1.w) + (a2.w + a3.w);
        zp[bg * 160 + f4] = r;
    }
    __syncthreads();

    if (t < 160) {
        float4 s = make_float4(0.f, 0.f, 0.f, 0.f);
        #pragma unroll
        for (int bg = 0; bg < 4; bg++) {
            const float4 v = zp[bg * 160 + t];
            s.x += v.x; s.y += v.y; s.z += v.z; s.w += v.w;
        }
        const float sc = 1.f / 1024.f;
        s.x *= sc; s.y *= sc; s.z *= sc; s.w *= sc;
        *(float4*)(dist + t * 4) = s;
    }
    __syncthreads();

    if (t < 32) {
        const int r2 = t;
        const int ra = r2 >> 3;
        float row[32];
        #pragma unroll
        for (int j = 0; j < 32; j++) {
            const int b = j >> 3;
            const int s = c_SLOT[ra * 4 + b];
            const int e = (ra <= b) ? ((r2 & 7) * 8 + (j & 7))
                                    : ((j & 7) * 8 + (r2 & 7));
            row[j] = __expf(-dist[s * 64 + e]);
        }
        const int pr = r2 ^ 16;              // positive partner (K=16)
        const float pos = row[pr];
        float m = pos;
        #pragma unroll
        for (int j = 0; j < 32; j++)
            if (j != r2 && j != pr) m = fmaxf(m, row[j]);
        float s = __expf(pos - m);
        #pragma unroll
        for (int j = 0; j < 32; j++)
            if (j != r2 && j != pr) s += __expf(row[j] - m);
        float rl = __logf(s) + m - pos;      // logsumexp - logits[:,0]

        #pragma unroll
        for (int off = 16; off > 0; off >>= 1)
            rl += __shfl_down_sync(0xFFFFFFFFu, rl, off);

        if (r2 == 0) out[0] = rl * (1.f / 32.f);
    }
}

// ---------------------------------------------------------------------------
extern "C" void kernel_launch(void* const* d_in, const int* in_sizes, int n_in,
                              void* d_out, int out_size)
{
    (void)in_sizes; (void)n_in; (void)out_size;
    const float* zi1 = (const float*)d_in[0];
    const float* zi2 = (const float*)d_in[1];
    const float* zj1 = (const float*)d_in[2];
    const float* zj2 = (const float*)d_in[3];
    float* out = (float*)d_out;

    const int smem = NROW * NSTRW * (int)sizeof(float);  // 132096 B dynamic
    cudaFuncSetAttribute(fused_kernel,
                         cudaFuncAttributeMaxDynamicSharedMemorySize, smem);

    fused_kernel<<<NBLK, NTHR, smem>>>(zi1, zi2, zj1, zj2);
    tail_kernel<<<1, 640>>>(out);
}